// round 2
// baseline (speedup 1.0000x reference)
#include <cuda_runtime.h>

// out[e] = dot(h[src[e]], h[dst[e]]), D_FEAT = 128, fp32.
// Indices are int32 (JAX x64 disabled -> int64 request silently demotes).
// One warp per edge: lane i loads float4 #i of each row (32*4 = 128 floats),
// 4-wide fma, then warp shuffle reduction.

#define D_FEAT 128

__global__ void __launch_bounds__(256)
edge_dot_kernel(const float* __restrict__ h,
                const int* __restrict__ src,
                const int* __restrict__ dst,
                float* __restrict__ out,
                int n_edges)
{
    int warp = (int)((blockIdx.x * (unsigned)blockDim.x + threadIdx.x) >> 5);
    int lane = threadIdx.x & 31;
    if (warp >= n_edges) return;

    int s = __ldg(&src[warp]);
    int d = __ldg(&dst[warp]);

    const float4* __restrict__ hs =
        reinterpret_cast<const float4*>(h + (long long)s * D_FEAT);
    const float4* __restrict__ hd =
        reinterpret_cast<const float4*>(h + (long long)d * D_FEAT);

    float4 a = __ldg(&hs[lane]);
    float4 b = __ldg(&hd[lane]);

    float acc = a.x * b.x;
    acc = fmaf(a.y, b.y, acc);
    acc = fmaf(a.z, b.z, acc);
    acc = fmaf(a.w, b.w, acc);

    // warp reduction
    #pragma unroll
    for (int off = 16; off > 0; off >>= 1)
        acc += __shfl_down_sync(0xFFFFFFFFu, acc, off);

    if (lane == 0)
        out[warp] = acc;
}

extern "C" void kernel_launch(void* const* d_in, const int* in_sizes, int n_in,
                              void* d_out, int out_size)
{
    const float* h   = (const float*)d_in[0];
    const int*   src = (const int*)d_in[1];
    const int*   dst = (const int*)d_in[2];
    float*       out = (float*)d_out;

    int n_edges = in_sizes[1];  // src element count

    const int threads = 256;            // 8 warps -> 8 edges per block
    int blocks = (n_edges + 7) / 8;
    edge_dot_kernel<<<blocks, threads>>>(h, src, dst, out, n_edges);
}

// round 3
// speedup vs baseline: 1.6709x; 1.6709x over previous
#include <cuda_runtime.h>

// out[e] = dot(h[src[e]], h[dst[e]]), D_FEAT = 128, fp32, int32 indices.
// 4 edges per warp, 8 lanes per edge. Each lane: 4 float4 from src row +
// 4 float4 from dst row (8 independent LDG.128 -> high MLP), 16 FMA,
// then 3-step width-8 shuffle reduction. ~3x fewer issued instructions
// per edge than warp-per-edge, same coalesced traffic.

#define D_FEAT 128

__global__ void __launch_bounds__(256)
edge_dot_kernel(const float* __restrict__ h,
                const int* __restrict__ src,
                const int* __restrict__ dst,
                float* __restrict__ out,
                int n_edges)
{
    int warp = (int)((blockIdx.x * (unsigned)blockDim.x + threadIdx.x) >> 5);
    int lane = threadIdx.x & 31;
    int grp  = lane >> 3;        // which of 4 edges in this warp
    int sub  = lane & 7;         // lane within the 8-lane group

    int e = warp * 4 + grp;
    if (e >= n_edges) return;

    int s = __ldg(&src[e]);
    int d = __ldg(&dst[e]);

    const float4* __restrict__ hs =
        reinterpret_cast<const float4*>(h + (long long)s * D_FEAT);
    const float4* __restrict__ hd =
        reinterpret_cast<const float4*>(h + (long long)d * D_FEAT);

    // 8 independent 16B loads; 8-lane group covers 512B row contiguously
    // per load instruction (lanes sub=0..7 -> one 128B segment each).
    float4 a0 = __ldg(&hs[sub]);
    float4 a1 = __ldg(&hs[sub +  8]);
    float4 a2 = __ldg(&hs[sub + 16]);
    float4 a3 = __ldg(&hs[sub + 24]);
    float4 b0 = __ldg(&hd[sub]);
    float4 b1 = __ldg(&hd[sub +  8]);
    float4 b2 = __ldg(&hd[sub + 16]);
    float4 b3 = __ldg(&hd[sub + 24]);

    float acc0 = a0.x * b0.x;
    acc0 = fmaf(a0.y, b0.y, acc0);
    acc0 = fmaf(a0.z, b0.z, acc0);
    acc0 = fmaf(a0.w, b0.w, acc0);

    float acc1 = a1.x * b1.x;
    acc1 = fmaf(a1.y, b1.y, acc1);
    acc1 = fmaf(a1.z, b1.z, acc1);
    acc1 = fmaf(a1.w, b1.w, acc1);

    float acc2 = a2.x * b2.x;
    acc2 = fmaf(a2.y, b2.y, acc2);
    acc2 = fmaf(a2.z, b2.z, acc2);
    acc2 = fmaf(a2.w, b2.w, acc2);

    float acc3 = a3.x * b3.x;
    acc3 = fmaf(a3.y, b3.y, acc3);
    acc3 = fmaf(a3.z, b3.z, acc3);
    acc3 = fmaf(a3.w, b3.w, acc3);

    float acc = (acc0 + acc1) + (acc2 + acc3);

    // width-8 reduction within the group
    acc += __shfl_down_sync(0xFFFFFFFFu, acc, 4, 8);
    acc += __shfl_down_sync(0xFFFFFFFFu, acc, 2, 8);
    acc += __shfl_down_sync(0xFFFFFFFFu, acc, 1, 8);

    if (sub == 0)
        out[e] = acc;
}

extern "C" void kernel_launch(void* const* d_in, const int* in_sizes, int n_in,
                              void* d_out, int out_size)
{
    const float* h   = (const float*)d_in[0];
    const int*   src = (const int*)d_in[1];
    const int*   dst = (const int*)d_in[2];
    float*       out = (float*)d_out;

    int n_edges = in_sizes[1];  // src element count

    const int threads = 256;                 // 8 warps -> 32 edges per block
    int blocks = (n_edges + 31) / 32;
    edge_dot_kernel<<<blocks, threads>>>(h, src, dst, out, n_edges);
}

// round 4
// speedup vs baseline: 1.6724x; 1.0009x over previous
#include <cuda_runtime.h>

// out[e] = dot(h[src[e]], h[dst[e]]), D_FEAT = 128, fp32, int32 indices.
// 8 edges per warp: each 8-lane group handles 2 edges (e0, e1 = e0+4).
// Per lane: 16 independent LDG.128 in flight (4 per row x 4 rows) -> high MLP
// to saturate the L2 gather path, then FMAs + width-8 shuffle reductions.

#define D_FEAT 128

__device__ __forceinline__ float dot4(float4 a, float4 b, float acc) {
    acc = fmaf(a.x, b.x, acc);
    acc = fmaf(a.y, b.y, acc);
    acc = fmaf(a.z, b.z, acc);
    acc = fmaf(a.w, b.w, acc);
    return acc;
}

__global__ void __launch_bounds__(256)
edge_dot_kernel(const float* __restrict__ h,
                const int* __restrict__ src,
                const int* __restrict__ dst,
                float* __restrict__ out,
                int n_edges)
{
    int warp = (int)((blockIdx.x * (unsigned)blockDim.x + threadIdx.x) >> 5);
    int lane = threadIdx.x & 31;
    int grp  = lane >> 3;        // 4 groups per warp
    int sub  = lane & 7;         // lane within 8-lane group

    int e0 = warp * 8 + grp;     // first edge of this group
    int e1 = e0 + 4;             // second edge of this group
    if (e0 >= n_edges) return;
    bool do1 = (e1 < n_edges);

    int s0 = __ldg(&src[e0]);
    int d0 = __ldg(&dst[e0]);
    int s1 = do1 ? __ldg(&src[e1]) : 0;
    int d1 = do1 ? __ldg(&dst[e1]) : 0;

    const float4* __restrict__ hs0 =
        reinterpret_cast<const float4*>(h + (long long)s0 * D_FEAT);
    const float4* __restrict__ hd0 =
        reinterpret_cast<const float4*>(h + (long long)d0 * D_FEAT);
    const float4* __restrict__ hs1 =
        reinterpret_cast<const float4*>(h + (long long)s1 * D_FEAT);
    const float4* __restrict__ hd1 =
        reinterpret_cast<const float4*>(h + (long long)d1 * D_FEAT);

    // Edge 0: 8 independent 16B loads (one 128B segment per load per group).
    float4 a0 = __ldg(&hs0[sub]);
    float4 a1 = __ldg(&hs0[sub +  8]);
    float4 a2 = __ldg(&hs0[sub + 16]);
    float4 a3 = __ldg(&hs0[sub + 24]);
    float4 b0 = __ldg(&hd0[sub]);
    float4 b1 = __ldg(&hd0[sub +  8]);
    float4 b2 = __ldg(&hd0[sub + 16]);
    float4 b3 = __ldg(&hd0[sub + 24]);

    // Edge 1: 8 more independent loads issued before consuming edge 0.
    float4 c0 = __ldg(&hs1[sub]);
    float4 c1 = __ldg(&hs1[sub +  8]);
    float4 c2 = __ldg(&hs1[sub + 16]);
    float4 c3 = __ldg(&hs1[sub + 24]);
    float4 g0 = __ldg(&hd1[sub]);
    float4 g1 = __ldg(&hd1[sub +  8]);
    float4 g2 = __ldg(&hd1[sub + 16]);
    float4 g3 = __ldg(&hd1[sub + 24]);

    float p0 = dot4(a0, b0, 0.0f);
    float p1 = dot4(a1, b1, 0.0f);
    float p2 = dot4(a2, b2, 0.0f);
    float p3 = dot4(a3, b3, 0.0f);
    float accA = (p0 + p1) + (p2 + p3);

    float q0 = dot4(c0, g0, 0.0f);
    float q1 = dot4(c1, g1, 0.0f);
    float q2 = dot4(c2, g2, 0.0f);
    float q3 = dot4(c3, g3, 0.0f);
    float accB = (q0 + q1) + (q2 + q3);

    // width-8 reductions (both edges reduced together)
    accA += __shfl_down_sync(0xFFFFFFFFu, accA, 4, 8);
    accB += __shfl_down_sync(0xFFFFFFFFu, accB, 4, 8);
    accA += __shfl_down_sync(0xFFFFFFFFu, accA, 2, 8);
    accB += __shfl_down_sync(0xFFFFFFFFu, accB, 2, 8);
    accA += __shfl_down_sync(0xFFFFFFFFu, accA, 1, 8);
    accB += __shfl_down_sync(0xFFFFFFFFu, accB, 1, 8);

    if (sub == 0) {
        out[e0] = accA;
        if (do1) out[e1] = accB;
    }
}

extern "C" void kernel_launch(void* const* d_in, const int* in_sizes, int n_in,
                              void* d_out, int out_size)
{
    const float* h   = (const float*)d_in[0];
    const int*   src = (const int*)d_in[1];
    const int*   dst = (const int*)d_in[2];
    float*       out = (float*)d_out;

    int n_edges = in_sizes[1];  // src element count

    const int threads = 256;                 // 8 warps -> 64 edges per block
    int blocks = (n_edges + 63) / 64;
    edge_dot_kernel<<<blocks, threads>>>(h, src, dst, out, n_edges);
}